// round 3
// baseline (speedup 1.0000x reference)
#include <cuda_runtime.h>
#include <cuda_bf16.h>
#include <cstdint>

// ---------------------------------------------------------------------------
// weighted_loss: fused per-row loss + global mean reduction.
//   pred [B,3] f32, true [B,3] f32, ot [B] i32  ->  scalar f32
// Memory-bound: 112 MiB read, one scalar write. Target ~17 us on GB300.
// ---------------------------------------------------------------------------

__device__ double g_acc;  // scratch accumulator (no allocations allowed)

// 1.1^k for k = 0..5
__constant__ float c_pow11[6] = {1.0f, 1.1f, 1.21f, 1.331f, 1.4641f, 1.61051f};
// chest OT scale
__constant__ float c_ot_scale[5] = {0.8f, 0.9f, 1.0f, 1.1f, 1.2f};

__global__ void zero_acc_kernel() { g_acc = 0.0; }

__device__ __forceinline__ int ais5(float x, float t0, float t1, float t2,
                                    float t3, float t4) {
    return (int)(x >= t0) + (int)(x >= t1) + (int)(x >= t2) +
           (int)(x >= t3) + (int)(x >= t4);
}

// w_mid = 1 + piecewise_linear(t, p, params, mid=1)
// a<b<c<d, k = ln2/d (reference: -log(0.5)/d). inv_a = 1/a, inv_cb = 1/(c-b).
__device__ __forceinline__ float w_mid(float t, float p, float a, float b,
                                       float c, float d, float k,
                                       float inv_a, float inv_cb) {
    // exp branch computed unconditionally; inf for small t is selected away.
    float we = __expf(-k * (t - d)) - 1.0f;
    float w;
    if (t > d)        w = we;
    else if (t >= c)  w = 0.0f;
    else if (t > b)   w = 1.0f - inv_cb * (t - b);
    else if (t >= a)  w = 1.0f;
    else if (t >= 0.f) w = inv_a * t;
    else              w = 0.0f;
    if (p < 0.0f) w += 1.0f;
    return 1.0f + w;
}

__device__ __forceinline__ float row_loss(float ph, float th,
                                          float pc, float tc,
                                          float pn, float tn,
                                          int ot) {
    // ---- HIC (head): a=80 b=1500 c=1750 d=2000, thr 150/500/1000/1800/2600
    int ap = ais5(ph, 150.f, 500.f, 1000.f, 1800.f, 2600.f);
    int at = ais5(th, 150.f, 500.f, 1000.f, 1800.f, 2600.f);
    float wcls = c_pow11[abs(ap - at)];
    float wm = w_mid(th, ph, 80.f, 1500.f, 1750.f, 2000.f,
                     3.46573590e-4f, 0.0125f, 0.004f);
    float loss = fabsf(ph - th) * wcls * wm;

    // ---- Dmax (chest): a=10 b=75 c=85 d=100, thr 22/35/45/55/65 * scale[ot]
    float s = c_ot_scale[ot];
    float u0 = 22.f * s, u1 = 35.f * s, u2 = 45.f * s, u3 = 55.f * s, u4 = 65.f * s;
    ap = ais5(pc, u0, u1, u2, u3, u4);
    at = ais5(tc, u0, u1, u2, u3, u4);
    wcls = c_pow11[abs(ap - at)];
    wm = w_mid(tc, pc, 10.f, 75.f, 85.f, 100.f,
               6.93147181e-3f, 0.1f, 0.1f);
    loss += fabsf(pc - tc) * wcls * wm;

    // ---- Nij (neck): a=0.15 b=1.5 c=1.7 d=1.9, thr 0.2/0.5/1/1.5/2
    ap = ais5(pn, 0.2f, 0.5f, 1.0f, 1.5f, 2.0f);
    at = ais5(tn, 0.2f, 0.5f, 1.0f, 1.5f, 2.0f);
    wcls = c_pow11[abs(ap - at)];
    wm = w_mid(tn, pn, 0.15f, 1.5f, 1.7f, 1.9f,
               0.364814311f, 6.66666651f, 5.0f);
    loss += fabsf(pn - tn) * wcls * wm;

    return loss;
}

__global__ __launch_bounds__(256)
void loss_kernel(const float* __restrict__ pred,
                 const float* __restrict__ tru,
                 const int*   __restrict__ ot,
                 int B) {
    const int tid = blockIdx.x * blockDim.x + threadIdx.x;
    const int r0 = tid * 4;

    float acc = 0.0f;
    if (r0 + 3 < B) {
        // 4 rows = 12 floats = 3 x float4 per array (16B aligned: 48B groups)
        const float4* p4 = reinterpret_cast<const float4*>(pred + (size_t)r0 * 3);
        const float4* t4 = reinterpret_cast<const float4*>(tru  + (size_t)r0 * 3);
        float4 pa = p4[0], pb = p4[1], pc4 = p4[2];
        float4 ta = t4[0], tb = t4[1], tc4 = t4[2];
        int4 o4 = *reinterpret_cast<const int4*>(ot + r0);

        acc += row_loss(pa.x, ta.x, pa.y, ta.y, pa.z, ta.z, o4.x);
        acc += row_loss(pa.w, ta.w, pb.x, tb.x, pb.y, tb.y, o4.y);
        acc += row_loss(pb.z, tb.z, pb.w, tb.w, pc4.x, tc4.x, o4.z);
        acc += row_loss(pc4.y, tc4.y, pc4.z, tc4.z, pc4.w, tc4.w, o4.w);
    } else {
        for (int r = r0; r < B; ++r) {
            acc += row_loss(pred[(size_t)r * 3 + 0], tru[(size_t)r * 3 + 0],
                            pred[(size_t)r * 3 + 1], tru[(size_t)r * 3 + 1],
                            pred[(size_t)r * 3 + 2], tru[(size_t)r * 3 + 2],
                            ot[r]);
        }
    }

    // warp reduce
    #pragma unroll
    for (int off = 16; off > 0; off >>= 1)
        acc += __shfl_xor_sync(0xffffffffu, acc, off);

    __shared__ float s_part[8];  // 256 threads = 8 warps
    const int lane = threadIdx.x & 31;
    const int warp = threadIdx.x >> 5;
    if (lane == 0) s_part[warp] = acc;
    __syncthreads();

    if (warp == 0) {
        float v = (lane < 8) ? s_part[lane] : 0.0f;
        #pragma unroll
        for (int off = 4; off > 0; off >>= 1)
            v += __shfl_xor_sync(0xffffffffu, v, off);
        if (lane == 0) atomicAdd(&g_acc, (double)v);
    }
}

__global__ void finalize_kernel(float* out, double inv_b) {
    out[0] = (float)(g_acc * inv_b);
}

extern "C" void kernel_launch(void* const* d_in, const int* in_sizes, int n_in,
                              void* d_out, int out_size) {
    const float* pred = (const float*)d_in[0];
    const float* tru  = (const float*)d_in[1];
    const int*   ot   = (const int*)d_in[2];
    float* out = (float*)d_out;

    const int B = in_sizes[2];           // rows
    const int threads = 256;
    const int rows_per_thread = 4;
    const int total_threads = (B + rows_per_thread - 1) / rows_per_thread;
    const int blocks = (total_threads + threads - 1) / threads;

    zero_acc_kernel<<<1, 1>>>();
    loss_kernel<<<blocks, threads>>>(pred, tru, ot, B);
    finalize_kernel<<<1, 1>>>(out, 1.0 / (double)B);
}